// round 4
// baseline (speedup 1.0000x reference)
#include <cuda_runtime.h>
#include <cuda_bf16.h>
#include <math.h>
#include <stdint.h>

// ---------------------------------------------------------------------------
// Shapes: b=2, L=4096, d=1024, h=16, n=p=64, chunk=64 -> tokens 8192, tiles 2048
// Output: y (8388608 f32) then final_state (131072 f32)
// ---------------------------------------------------------------------------
#define NTOK   8192
#define DMOD   1024
#define NHEADS 16
#define NTILE  2048
#define Y_ELEMS 8388608
#define PROJN  4352    // 2048 (xz) + 1024 (B) + 1024 (C) + 16 (dt) + 240 pad

// fp32 scratch
__device__ float gProj[NTOK * PROJN];    // [tok][xz | B | C | dtraw | pad]
__device__ float gYdiag[NTILE * 4096];
__device__ float gStates[NTILE * 4096];
__device__ float gStateIn[NTILE * 4096];
__device__ float gAlast[NTILE];

// bf16 hi/lo operand scratch
__device__ __nv_bfloat16 gXhi[NTOK * DMOD], gXlo[NTOK * DMOD];
__device__ __nv_bfloat16 gWcatHi[PROJN * DMOD], gWcatLo[PROJN * DMOD];  // pad rows stay 0
__device__ __nv_bfloat16 gWoHi[DMOD * DMOD], gWoLo[DMOD * DMOD];
__device__ __nv_bfloat16 gYaHi[NTOK * DMOD], gYaLo[NTOK * DMOD];

// ---------------------------------------------------------------------------
// PTX helpers (sm_80-level only: cp.async, ldmatrix, mma.sync)
// ---------------------------------------------------------------------------
__device__ __forceinline__ uint32_t smem_u32(const void* p) {
    uint32_t a;
    asm("{ .reg .u64 t; cvta.to.shared.u64 t, %1; cvt.u32.u64 %0, t; }" : "=r"(a) : "l"(p));
    return a;
}
__device__ __forceinline__ void cp16(uint32_t dst, const void* src) {
    asm volatile("cp.async.cg.shared.global [%0], [%1], 16;\n" :: "r"(dst), "l"(src));
}
__device__ __forceinline__ void cp_commit() { asm volatile("cp.async.commit_group;\n" ::: "memory"); }
template <int N> __device__ __forceinline__ void cp_wait() {
    asm volatile("cp.async.wait_group %0;\n" :: "n"(N) : "memory");
}
__device__ __forceinline__ void ldsm4(uint32_t* r, uint32_t addr) {
    asm volatile("ldmatrix.sync.aligned.m8n8.x4.shared.b16 {%0,%1,%2,%3}, [%4];"
                 : "=r"(r[0]), "=r"(r[1]), "=r"(r[2]), "=r"(r[3]) : "r"(addr));
}
__device__ __forceinline__ void mma16816(float* d, const uint32_t* a, const uint32_t* b) {
    asm volatile("mma.sync.aligned.m16n8k16.row.col.f32.bf16.bf16.f32 "
                 "{%0,%1,%2,%3}, {%4,%5,%6,%7}, {%8,%9}, {%0,%1,%2,%3};"
                 : "+f"(d[0]), "+f"(d[1]), "+f"(d[2]), "+f"(d[3])
                 : "r"(a[0]), "r"(a[1]), "r"(a[2]), "r"(a[3]), "r"(b[0]), "r"(b[1]));
}

// ---------------------------------------------------------------------------
// Tensor-core GEMM: C[M,N] = A[M,K] @ B[N,K]^T, fp32 via bf16 hi/lo 3-term.
// CTA tile 128x256, K chunk 32, 3-stage cp.async pipeline, 8 warps (2m x 4n),
// warp tile 64x64. SMEM rows are 64B (k32), swizzle: chunk ^= (row>>1)&3.
// ---------------------------------------------------------------------------
#define TM 128
#define TN 256
#define SOF_AH 0
#define SOF_AL (TM * 64)
#define SOF_BH (2 * TM * 64)
#define SOF_BL (2 * TM * 64 + TN * 64)
#define STAGE_SZ (2 * TM * 64 + 2 * TN * 64)   // 49152
#define GEMM_SMEM (3 * STAGE_SZ)               // 147456

__device__ __forceinline__ void load_t32(uint32_t dst, const __nv_bfloat16* g,
                                         int row0, int K, int k0, int rows, int t) {
    for (int p = t; p < rows * 4; p += 256) {
        int r = p >> 2, c = p & 3;
        uint32_t off = (uint32_t)(r * 64) + (uint32_t)((c ^ ((r >> 1) & 3)) << 4);
        cp16(dst + off, g + (size_t)(row0 + r) * K + k0 + c * 8);
    }
}

__global__ __launch_bounds__(256, 1)
void gemm_mma(const __nv_bfloat16* __restrict__ Ah, const __nv_bfloat16* __restrict__ Al,
              const __nv_bfloat16* __restrict__ Bh, const __nv_bfloat16* __restrict__ Bl,
              float* __restrict__ C, int M, int N, int K) {
    extern __shared__ char smem[];
    const uint32_t sb = smem_u32(smem);
    const int t = threadIdx.x;
    const int wid = t >> 5, lane = t & 31;
    const int bm = blockIdx.y * TM;
    const int bn = blockIdx.x * TN;
    const int wm = (wid >> 2) * 64;
    const int wn = (wid & 3) * 64;
    const int nch = K >> 5;   // k32 chunks

    float acc[4][8][4];
#pragma unroll
    for (int i = 0; i < 4; i++)
#pragma unroll
        for (int j = 0; j < 8; j++)
#pragma unroll
            for (int k = 0; k < 4; k++) acc[i][j][k] = 0.f;

    // prologue: chunks 0,1 -> stages 0,1
#pragma unroll
    for (int pc = 0; pc < 2; pc++) {
        uint32_t st = sb + pc * STAGE_SZ;
        int k0 = pc * 32;
        load_t32(st + SOF_AH, Ah, bm, K, k0, TM, t);
        load_t32(st + SOF_AL, Al, bm, K, k0, TM, t);
        load_t32(st + SOF_BH, Bh, bn, K, k0, TN, t);
        load_t32(st + SOF_BL, Bl, bn, K, k0, TN, t);
        cp_commit();
    }

    // precomputed ldsm lane address pieces
    const int ra = (lane & 15);                                   // A row within 16
    const uint32_t ca = (uint32_t)((lane >> 4) << 4);             // A col byte (within k16)
    const int rb = (lane & 7) + (((lane >> 4) & 1) << 3);         // B row within 16
    const uint32_t cb = (uint32_t)(((lane >> 3) & 1) << 4);       // B col byte

    int stage = 0;
    for (int i = 0; i < nch; i++) {
        __syncthreads();   // everyone done with stage (i+2)%3's old data
        if (i + 2 < nch) {
            uint32_t st2 = sb + ((stage + 2) % 3) * STAGE_SZ;
            int k0 = (i + 2) * 32;
            load_t32(st2 + SOF_AH, Ah, bm, K, k0, TM, t);
            load_t32(st2 + SOF_AL, Al, bm, K, k0, TM, t);
            load_t32(st2 + SOF_BH, Bh, bn, K, k0, TN, t);
            load_t32(st2 + SOF_BL, Bl, bn, K, k0, TN, t);
            cp_commit();
            cp_wait<2>();
        } else {
            cp_wait<0>();
        }
        __syncthreads();   // chunk i visible to all

        const uint32_t st = sb + stage * STAGE_SZ;
#pragma unroll
        for (int w = 0; w < 2; w++) {     // two k16 halves of the k32 chunk
            uint32_t ah[4][4], al[4][4], bh[4][4], bl[4][4];
#pragma unroll
            for (int mi = 0; mi < 4; mi++) {
                int r = wm + mi * 16 + ra;
                uint32_t col = (uint32_t)(w * 32) + ca;
                uint32_t off = (uint32_t)(r * 64) + (col ^ (uint32_t)(((r >> 1) & 3) << 4));
                ldsm4(ah[mi], st + SOF_AH + off);
                ldsm4(al[mi], st + SOF_AL + off);
            }
#pragma unroll
            for (int nb = 0; nb < 4; nb++) {
                int r = wn + nb * 16 + rb;
                uint32_t col = (uint32_t)(w * 32) + cb;
                uint32_t off = (uint32_t)(r * 64) + (col ^ (uint32_t)(((r >> 1) & 3) << 4));
                ldsm4(bh[nb], st + SOF_BH + off);
                ldsm4(bl[nb], st + SOF_BL + off);
            }
#pragma unroll
            for (int mi = 0; mi < 4; mi++)
#pragma unroll
                for (int ni = 0; ni < 8; ni++) {
                    const uint32_t* h2 = &bh[ni >> 1][(ni & 1) * 2];
                    const uint32_t* l2 = &bl[ni >> 1][(ni & 1) * 2];
                    mma16816(acc[mi][ni], ah[mi], h2);
                    mma16816(acc[mi][ni], ah[mi], l2);
                    mma16816(acc[mi][ni], al[mi], h2);
                }
        }
        stage = (stage + 1) % 3;
    }

    // epilogue
#pragma unroll
    for (int mi = 0; mi < 4; mi++) {
        int r0 = bm + wm + mi * 16 + (lane >> 2);
#pragma unroll
        for (int ni = 0; ni < 8; ni++) {
            int c0 = bn + wn + ni * 8 + ((lane & 3) << 1);
            *(float2*)&C[(size_t)r0 * N + c0] = make_float2(acc[mi][ni][0], acc[mi][ni][1]);
            *(float2*)&C[(size_t)(r0 + 8) * N + c0] = make_float2(acc[mi][ni][2], acc[mi][ni][3]);
        }
    }
}

// ---------------------------------------------------------------------------
// fp32 -> bf16 hi/lo split
// ---------------------------------------------------------------------------
__global__ __launch_bounds__(256)
void cvt_hilo(const float* __restrict__ src, __nv_bfloat16* __restrict__ hi,
              __nv_bfloat16* __restrict__ lo, int n4) {
    int i = blockIdx.x * 256 + threadIdx.x;
    if (i >= n4) return;
    float4 v = ((const float4*)src)[i];
    __nv_bfloat16 h0 = __float2bfloat16(v.x), h1 = __float2bfloat16(v.y);
    __nv_bfloat16 h2 = __float2bfloat16(v.z), h3 = __float2bfloat16(v.w);
    __nv_bfloat162* hp = (__nv_bfloat162*)hi;
    __nv_bfloat162* lp = (__nv_bfloat162*)lo;
    hp[2 * i]     = __nv_bfloat162(h0, h1);
    hp[2 * i + 1] = __nv_bfloat162(h2, h3);
    lp[2 * i]     = __nv_bfloat162(__float2bfloat16(v.x - __bfloat162float(h0)),
                                   __float2bfloat16(v.y - __bfloat162float(h1)));
    lp[2 * i + 1] = __nv_bfloat162(__float2bfloat16(v.z - __bfloat162float(h2)),
                                   __float2bfloat16(v.w - __bfloat162float(h3)));
}

// ---------------------------------------------------------------------------
// SSD pass 1: per (b, chunk, head) tile -> Y_diag, chunk-end states, A_last
// ---------------------------------------------------------------------------
__global__ __launch_bounds__(256)
void ssd_pass1(const float* __restrict__ Alog, const float* __restrict__ bdt) {
    extern __shared__ float sm[];
    float* sB = sm;
    float* sC = sm + 64 * 65;
    float* sX = sm + 2 * 64 * 65;
    __shared__ float sdt[64];
    __shared__ float sacum[64];
    __shared__ float sdec[64];

    const int tile = blockIdx.x;
    const int h = tile & 15;
    const int c = (tile >> 4) & 63;
    const int b = tile >> 10;
    const int t = threadIdx.x;
    const int tokb = b * 4096 + c * 64;

    if (t < 64) {
        float v = gProj[(size_t)(tokb + t) * PROJN + 4096 + h] + bdt[h];
        sdt[t] = (v > 20.f) ? v : log1pf(expf(v));
    }
    __syncthreads();
    if (t == 0) {
        float expA = expf(Alog[h]);
        float run = 0.f;
        for (int l = 0; l < 64; l++) { run -= expA * sdt[l]; sacum[l] = run; }
    }
#pragma unroll
    for (int k = 0; k < 16; k++) {
        int idx = t + k * 256;
        int l = idx >> 6, n = idx & 63;
        size_t tok = (size_t)(tokb + l);
        sB[l * 65 + n] = gProj[tok * PROJN + 2048 + h * 64 + n];
        sC[l * 65 + n] = gProj[tok * PROJN + 3072 + h * 64 + n];
        sX[l * 65 + n] = gProj[tok * PROJN + h * 64 + n] * sdt[l];
    }
    __syncthreads();
    if (t < 64) sdec[t] = expf(sacum[63] - sacum[t]);

    const int ty = t >> 4, tx = t & 15;
    const int r0 = ty * 4, c0 = tx * 4;

    float g[4][4] = {};
#pragma unroll 4
    for (int n = 0; n < 64; n++) {
        float a[4], bb[4];
#pragma unroll
        for (int i = 0; i < 4; i++) a[i]  = sC[(r0 + i) * 65 + n];
#pragma unroll
        for (int j = 0; j < 4; j++) bb[j] = sB[(c0 + j) * 65 + n];
#pragma unroll
        for (int i = 0; i < 4; i++)
#pragma unroll
            for (int j = 0; j < 4; j++) g[i][j] += a[i] * bb[j];
    }
#pragma unroll
    for (int i = 0; i < 4; i++)
#pragma unroll
        for (int j = 0; j < 4; j++) {
            int l = r0 + i, s = c0 + j;
            g[i][j] = (s <= l) ? g[i][j] * expf(sacum[l] - sacum[s]) : 0.f;
        }
    __syncthreads();
#pragma unroll
    for (int i = 0; i < 4; i++)
#pragma unroll
        for (int j = 0; j < 4; j++) sC[(r0 + i) * 65 + c0 + j] = g[i][j];
    __syncthreads();

    float yd[4][4] = {};
#pragma unroll 4
    for (int s = 0; s < 64; s++) {
        float a[4], bb[4];
#pragma unroll
        for (int i = 0; i < 4; i++) a[i]  = sC[(r0 + i) * 65 + s];
#pragma unroll
        for (int j = 0; j < 4; j++) bb[j] = sX[s * 65 + c0 + j];
#pragma unroll
        for (int i = 0; i < 4; i++)
#pragma unroll
            for (int j = 0; j < 4; j++) yd[i][j] += a[i] * bb[j];
    }
    float st[4][4] = {};
#pragma unroll 4
    for (int l = 0; l < 64; l++) {
        float d = sdec[l];
        float a[4], bb[4];
#pragma unroll
        for (int i = 0; i < 4; i++) a[i]  = sX[l * 65 + r0 + i] * d;
#pragma unroll
        for (int j = 0; j < 4; j++) bb[j] = sB[l * 65 + c0 + j];
#pragma unroll
        for (int i = 0; i < 4; i++)
#pragma unroll
            for (int j = 0; j < 4; j++) st[i][j] += a[i] * bb[j];
    }
    size_t obase = (size_t)tile * 4096;
#pragma unroll
    for (int i = 0; i < 4; i++)
#pragma unroll
        for (int j = 0; j < 4; j++) {
            gYdiag[obase + (r0 + i) * 64 + c0 + j]  = yd[i][j];
            gStates[obase + (r0 + i) * 64 + c0 + j] = st[i][j];
        }
    if (t == 0) gAlast[tile] = sacum[63];
}

// ---------------------------------------------------------------------------
// Chunk-level scan, one element per thread (512 CTAs x 256 thr = 131072 lanes)
// ---------------------------------------------------------------------------
__global__ __launch_bounds__(256)
void scan_kernel(float* __restrict__ out_final) {
    const int bh = blockIdx.x >> 4;
    const int b = bh >> 4, h = bh & 15;
    const int e = ((blockIdx.x & 15) << 8) | threadIdx.x;
    float S = 0.f;
#pragma unroll 4
    for (int c = 0; c < 64; c++) {
        int tile = (b * 64 + c) * 16 + h;
        float d = expf(gAlast[tile]);
        size_t base = (size_t)tile * 4096 + e;
        gStateIn[base] = S;
        S = S * d + gStates[base];
    }
    out_final[(size_t)Y_ELEMS + (size_t)(b * 16 + h) * 4096 + e] = S;
}

// ---------------------------------------------------------------------------
// SSD pass 2: Y_off + silu gating; writes bf16 hi/lo for the final GEMM
// ---------------------------------------------------------------------------
__global__ __launch_bounds__(256)
void ssd_pass2(const float* __restrict__ Alog, const float* __restrict__ bdt) {
    __shared__ float sC[64 * 65];
    __shared__ float sS[64 * 65];
    __shared__ float sdt[64];
    __shared__ float sacum[64];

    const int tile = blockIdx.x;
    const int h = tile & 15;
    const int c = (tile >> 4) & 63;
    const int b = tile >> 10;
    const int t = threadIdx.x;
    const int tokb = b * 4096 + c * 64;

    if (t < 64) {
        float v = gProj[(size_t)(tokb + t) * PROJN + 4096 + h] + bdt[h];
        sdt[t] = (v > 20.f) ? v : log1pf(expf(v));
    }
    __syncthreads();
    if (t == 0) {
        float expA = expf(Alog[h]);
        float run = 0.f;
        for (int l = 0; l < 64; l++) { run -= expA * sdt[l]; sacum[l] = run; }
    }
    size_t sbase = (size_t)tile * 4096;
#pragma unroll
    for (int k = 0; k < 16; k++) {
        int idx = t + k * 256;
        int l = idx >> 6, n = idx & 63;
        sC[l * 65 + n] = gProj[(size_t)(tokb + l) * PROJN + 3072 + h * 64 + n];
        sS[l * 65 + n] = gStateIn[sbase + idx];
    }
    __syncthreads();

    const int ty = t >> 4, tx = t & 15;
    const int r0 = ty * 4, c0 = tx * 4;
    float o[4][4] = {};
#pragma unroll 4
    for (int n = 0; n < 64; n++) {
        float a[4], bb[4];
#pragma unroll
        for (int i = 0; i < 4; i++) a[i]  = sC[(r0 + i) * 65 + n];
#pragma unroll
        for (int j = 0; j < 4; j++) bb[j] = sS[(c0 + j) * 65 + n];
#pragma unroll
        for (int i = 0; i < 4; i++)
#pragma unroll
            for (int j = 0; j < 4; j++) o[i][j] += a[i] * bb[j];
    }
#pragma unroll
    for (int i = 0; i < 4; i++) {
        int l = r0 + i;
        size_t tok = (size_t)(tokb + l);
        float eA = expf(sacum[l]);
#pragma unroll
        for (int j = 0; j < 4; j++) {
            int p = c0 + j;
            int dcol = h * 64 + p;
            float yv = gYdiag[sbase + l * 64 + p] + o[i][j] * eA;
            float zv = gProj[tok * PROJN + 1024 + dcol];
            float sig = 1.f / (1.f + expf(-zv));
            float y = yv * (zv * sig);
            __nv_bfloat16 hh = __float2bfloat16(y);
            gYaHi[tok * DMOD + dcol] = hh;
            gYaLo[tok * DMOD + dcol] = __float2bfloat16(y - __bfloat162float(hh));
        }
    }
}

// ---------------------------------------------------------------------------
extern "C" void kernel_launch(void* const* d_in, const int* in_sizes, int n_in,
                              void* d_out, int out_size) {
    const float* x     = (const float*)d_in[0];
    const float* W_in  = (const float*)d_in[1];
    const float* W_dt  = (const float*)d_in[2];
    const float* b_dt  = (const float*)d_in[3];
    const float* W_B   = (const float*)d_in[4];
    const float* W_C   = (const float*)d_in[5];
    const float* W_out = (const float*)d_in[6];
    const float* A_log = (const float*)d_in[7];
    float* out = (float*)d_out;

    void *pProj;
    cudaGetSymbolAddress(&pProj, gProj);
    void *pXhi, *pXlo, *pWcH, *pWcL, *pWoH, *pWoL, *pYaH, *pYaL;
    cudaGetSymbolAddress(&pXhi, gXhi);   cudaGetSymbolAddress(&pXlo, gXlo);
    cudaGetSymbolAddress(&pWcH, gWcatHi); cudaGetSymbolAddress(&pWcL, gWcatLo);
    cudaGetSymbolAddress(&pWoH, gWoHi);  cudaGetSymbolAddress(&pWoL, gWoLo);
    cudaGetSymbolAddress(&pYaH, gYaHi);  cudaGetSymbolAddress(&pYaL, gYaLo);

    cudaFuncSetAttribute(gemm_mma, cudaFuncAttributeMaxDynamicSharedMemorySize, GEMM_SMEM);
    const int P1_SHMEM = 3 * 64 * 65 * (int)sizeof(float);
    cudaFuncSetAttribute(ssd_pass1, cudaFuncAttributeMaxDynamicSharedMemorySize, P1_SHMEM);

    __nv_bfloat16* WcH = (__nv_bfloat16*)pWcH;
    __nv_bfloat16* WcL = (__nv_bfloat16*)pWcL;

    // hi/lo conversions (weights packed into gWcat at row offsets)
    cvt_hilo<<<(NTOK * DMOD / 4 + 255) / 256, 256>>>(x, (__nv_bfloat16*)pXhi, (__nv_bfloat16*)pXlo, NTOK * DMOD / 4);
    cvt_hilo<<<(2048 * DMOD / 4 + 255) / 256, 256>>>(W_in, WcH, WcL, 2048 * DMOD / 4);
    cvt_hilo<<<(DMOD * DMOD / 4 + 255) / 256, 256>>>(W_B, WcH + 2048 * DMOD, WcL + 2048 * DMOD, DMOD * DMOD / 4);
    cvt_hilo<<<(DMOD * DMOD / 4 + 255) / 256, 256>>>(W_C, WcH + 3072 * DMOD, WcL + 3072 * DMOD, DMOD * DMOD / 4);
    cvt_hilo<<<(16 * DMOD / 4 + 255) / 256, 256>>>(W_dt, WcH + 4096 * DMOD, WcL + 4096 * DMOD, 16 * DMOD / 4);
    cvt_hilo<<<(DMOD * DMOD / 4 + 255) / 256, 256>>>(W_out, (__nv_bfloat16*)pWoH, (__nv_bfloat16*)pWoL, DMOD * DMOD / 4);

    // combined projection GEMM: [8192 x 4352 x 1024] -> gProj
    gemm_mma<<<dim3(PROJN / TN, NTOK / TM), 256, GEMM_SMEM>>>(
        (const __nv_bfloat16*)pXhi, (const __nv_bfloat16*)pXlo,
        WcH, WcL, (float*)pProj, NTOK, PROJN, DMOD);

    ssd_pass1<<<NTILE, 256, P1_SHMEM>>>(A_log, b_dt);
    scan_kernel<<<512, 256>>>(out);
    ssd_pass2<<<NTILE, 256>>>(A_log, b_dt);

    // y = Yact @ W_out^T -> d_out
    gemm_mma<<<dim3(DMOD / TN, NTOK / TM), 256, GEMM_SMEM>>>(
        (const __nv_bfloat16*)pYaH, (const __nv_bfloat16*)pYaL,
        (const __nv_bfloat16*)pWoH, (const __nv_bfloat16*)pWoL,
        out, NTOK, DMOD, DMOD);
}